// round 14
// baseline (speedup 1.0000x reference)
#include <cuda_runtime.h>
#include <cuda_bf16.h>
#include <math.h>

// Problem constants
#define NF   16384
#define HID  64
#define TH   192          // 3*HID rows of U per feature
#define FPB  4            // features per block (fine-grained tail)
#define NBLK (NF / FPB)   // 4096
#define BTH  256          // 8 warps; warp w owns gates [8w, 8w+8)

// Static scratch
__device__ float g_partial_agg[NBLK * HID];
__device__ int   g_total_cnt;     // written by setup_kernel (pre-main)
__device__ int   g_mask_mode;

__device__ __forceinline__ float dot4(float4 a, float4 b) {
    return a.x * b.x + a.y * b.y + a.z * b.z + a.w * b.w;
}

__device__ __forceinline__ bool mask_at(const void* mp, int mode, int f) {
    if (mode == 0) return ((const unsigned char*)mp)[f] != 0;
    if (mode == 1) return ((const int*)mp)[f] != 0;
    return ((const float*)mp)[f] != 0.0f;
}

__device__ __forceinline__ float red8(float v) {
    v += __shfl_xor_sync(0xFFFFFFFFu, v, 1);
    v += __shfl_xor_sync(0xFFFFFFFFu, v, 2);
    v += __shfl_xor_sync(0xFFFFFFFFu, v, 4);
    return v;
}

// ---------------------------------------------------------------------------
// Kernel 0: detect mask representation (0=u8 bool, 1=i32, 2=f32) AND count
// set mask bits. One block, 256 threads; runs before the main kernel so the
// no-mask fallback can be folded into the main store (no fixup kernel).
// ---------------------------------------------------------------------------
__global__ __launch_bounds__(256) void setup_kernel(const void* __restrict__ mask)
{
    __shared__ int s_isf, s_isu8, s_cnt;
    const int t = threadIdx.x;

    if (t == 0) { s_isf = 0; s_isu8 = 0; s_cnt = 0; }
    __syncthreads();

    // representation probe on the first 256 bytes / 64 words
    {
        const unsigned int*  mw = (const unsigned int*)mask;
        const unsigned char* mb = (const unsigned char*)mask;
        if (t < 64 && mw[t] == 0x3F800000u) atomicOr(&s_isf, 1);
        if ((t & 3) != 0 && mb[t] != 0)     atomicOr(&s_isu8, 1);
    }
    __syncthreads();
    const int mode = s_isf ? 2 : (s_isu8 ? 0 : 1);
    if (t == 0) g_mask_mode = mode;

    // count all NF mask entries (64 per thread)
    int c = 0;
    #pragma unroll 4
    for (int f = t; f < NF; f += 256) c += (int)mask_at(mask, mode, f);
    c += __shfl_xor_sync(0xFFFFFFFFu, c, 1);
    c += __shfl_xor_sync(0xFFFFFFFFu, c, 2);
    c += __shfl_xor_sync(0xFFFFFFFFu, c, 4);
    c += __shfl_xor_sync(0xFFFFFFFFu, c, 8);
    c += __shfl_xor_sync(0xFFFFFFFFu, c, 16);
    if ((t & 31) == 0) atomicAdd(&s_cnt, c);
    __syncthreads();
    if (t == 0) g_total_cnt = s_cnt;
}

// ---------------------------------------------------------------------------
// Kernel 1: per-feature GRU cell — barrier-free main loop.
// Warp w owns gates g0 = 8w+rsub, g1 = g0+4 (rsub = lane>>3). Its 6 row-dots
// per feature are exactly the z/r/h rows of those two gates. 8 lanes per row
// (q = lane&7 reads the q-th float4 of each 128B half-row) -> every LDG.128
// covers 4 rows x one full 128B line. 3-level shfl.xor gives all lanes all
// 6 dots; lanes q=0/q=1 finish gates g0/g1 entirely in registers.
// The no-mask fallback (H_curr = Ht when no feature masked) is folded into
// the store: mv ? hg : (any ? 0 : htg). No fixup kernel.
// ---------------------------------------------------------------------------
__global__ __launch_bounds__(BTH, 4) void gru_main_kernel(
    const float* __restrict__ X,
    const void*  __restrict__ mask,
    const float* __restrict__ Ht,
    const float* __restrict__ xT_w,   // (F, 192, 1)
    const float* __restrict__ xT_b,   // (F, 192)
    const float* __restrict__ U_w,    // (F, 192, 64)
    float*       __restrict__ H_curr) // (F, 64)
{
    const int t    = threadIdx.x;
    const int w    = t >> 5;
    const int l    = t & 31;
    const int q    = l & 7;
    const int rsub = l >> 3;
    const int g0   = 8 * w + rsub;
    const int g1   = g0 + 4;
    const int g    = (q == 0) ? g0 : g1;   // gate owned by lanes q<2

    const int  mode = g_mask_mode;         // broadcast, set by setup_kernel
    const bool any  = (g_total_cnt > 0);   // broadcast, set by setup_kernel

    float agg0 = 0.0f, agg1 = 0.0f;

    #pragma unroll 1
    for (int j = 0; j < FPB; j++) {
        const int f = blockIdx.x * FPB + j;

        // Ht slices first: they sit on the FFMA dependency chain
        const float4* Ht4 = (const float4*)(Ht + (size_t)f * HID);
        const float4  h0  = Ht4[q];
        const float4  h1  = Ht4[8 + q];

        // 12 front-batched streaming LDG.128 (rows of this warp's two gates)
        const float4* Ub = (const float4*)(U_w + (size_t)f * TH * HID);
        const float4 uA0 = __ldcs(Ub + (g0      ) * 16 + q);
        const float4 uB0 = __ldcs(Ub + (g0      ) * 16 + 8 + q);
        const float4 uA1 = __ldcs(Ub + (g0 +  64) * 16 + q);
        const float4 uB1 = __ldcs(Ub + (g0 +  64) * 16 + 8 + q);
        const float4 uA2 = __ldcs(Ub + (g0 + 128) * 16 + q);
        const float4 uB2 = __ldcs(Ub + (g0 + 128) * 16 + 8 + q);
        const float4 uA3 = __ldcs(Ub + (g1      ) * 16 + q);
        const float4 uB3 = __ldcs(Ub + (g1      ) * 16 + 8 + q);
        const float4 uA4 = __ldcs(Ub + (g1 +  64) * 16 + q);
        const float4 uB4 = __ldcs(Ub + (g1 +  64) * 16 + 8 + q);
        const float4 uA5 = __ldcs(Ub + (g1 + 128) * 16 + q);
        const float4 uB5 = __ldcs(Ub + (g1 + 128) * 16 + 8 + q);

        // Gate-lane scalars (independent; small L1-shared lines)
        float xz = 0.f, xr = 0.f, xh = 0.f, htg = 0.f;
        bool  mv = false;
        if (q < 2) {
            const float xf = X[f];
            const float* xw = xT_w + (size_t)f * TH;
            const float* xb = xT_b + (size_t)f * TH;
            xz  = fmaf(xw[g],       xf, xb[g]);
            xr  = fmaf(xw[g + 64],  xf, xb[g + 64]);
            xh  = fmaf(xw[g + 128], xf, xb[g + 128]);
            htg = Ht[(size_t)f * HID + g];
            mv  = mask_at(mask, mode, f);
        }

        float d0 = dot4(uA0, h0) + dot4(uB0, h1);
        float d1 = dot4(uA1, h0) + dot4(uB1, h1);
        float d2 = dot4(uA2, h0) + dot4(uB2, h1);
        float d3 = dot4(uA3, h0) + dot4(uB3, h1);
        float d4 = dot4(uA4, h0) + dot4(uB4, h1);
        float d5 = dot4(uA5, h0) + dot4(uB5, h1);

        d0 = red8(d0); d1 = red8(d1); d2 = red8(d2);
        d3 = red8(d3); d4 = red8(d4); d5 = red8(d5);

        if (q < 2) {
            const float uz = (q == 0) ? d0 : d3;
            const float ur = (q == 0) ? d1 : d4;
            const float uh = (q == 0) ? d2 : d5;

            const float z   = 1.0f / (1.0f + __expf(-(xz + uz)));
            const float r   = 1.0f / (1.0f + __expf(-(xr + ur)));
            const float htl = tanhf(xh + r * uh);
            const float hg  = z * htg + (1.0f - z) * htl;

            // reference: H_curr = where(mask, h_gate, 0); where(any, ., Ht)
            const float outv = mv ? hg : (any ? 0.0f : htg);
            __stcs(H_curr + (size_t)f * HID + g, outv);
            const float add = mv ? hg : 0.0f;
            if (q == 0) agg0 += add; else agg1 += add;
        }
    }

    if (q == 0) g_partial_agg[blockIdx.x * HID + g0] = agg0;
    if (q == 1) g_partial_agg[blockIdx.x * HID + g1] = agg1;
}

// ---------------------------------------------------------------------------
// Kernel 2: reduce partials (coalesced 16-slice), MLP head, softmax.
// Count comes from setup_kernel via g_total_cnt.
// ---------------------------------------------------------------------------
__global__ __launch_bounds__(1024) void finalize_kernel(
    const float* __restrict__ W1,
    const float* __restrict__ b1,
    const float* __restrict__ W2,
    const float* __restrict__ b2,
    float*       __restrict__ out)
{
    __shared__ float red[16][HID];
    __shared__ float sAgg[HID];
    __shared__ float sHid[HID];

    const int t  = threadIdx.x;
    const int h  = t & 63;
    const int sl = t >> 6;

    float a = 0.0f;
    #pragma unroll 8
    for (int bb = sl; bb < NBLK; bb += 16) a += g_partial_agg[bb * HID + h];
    red[sl][h] = a;
    __syncthreads();

    if (t < HID) {
        float s = 0.0f;
        #pragma unroll
        for (int i = 0; i < 16; i++) s += red[i][t];
        sAgg[t] = s / fmaxf((float)g_total_cnt, 1.0f);
    }
    __syncthreads();

    if (t < HID) {
        float acc = b1[t];
        #pragma unroll 8
        for (int k = 0; k < HID; k++) acc += sAgg[k] * W1[k * HID + t];
        sHid[t] = fmaxf(acc, 0.0f);
    }
    __syncthreads();

    if (t == 0) {
        float l0 = b2[0], l1 = b2[1];
        #pragma unroll 8
        for (int j = 0; j < HID; j++) {
            l0 += sHid[j] * W2[j * 2 + 0];
            l1 += sHid[j] * W2[j * 2 + 1];
        }
        const float mx = fmaxf(l0, l1);
        const float e0 = expf(l0 - mx), e1 = expf(l1 - mx);
        const float inv = 1.0f / (e0 + e1);
        out[0] = e0 * inv;
        out[1] = e1 * inv;
    }
}

// ---------------------------------------------------------------------------
// Launch.  Inputs: tim, X, X_hap, mask, Ht, xT_w, xT_b, U_w, W1, b1, W2, b2.
// Output: [pred(2), H_curr(16384*64)] float32.
// ---------------------------------------------------------------------------
extern "C" void kernel_launch(void* const* d_in, const int* in_sizes, int n_in,
                              void* d_out, int out_size)
{
    const float* X     = (const float*)d_in[1];
    const void*  mask  = d_in[3];
    const float* Ht    = (const float*)d_in[4];
    const float* xT_w  = (const float*)d_in[5];
    const float* xT_b  = (const float*)d_in[6];
    const float* U_w   = (const float*)d_in[7];
    const float* W1    = (const float*)d_in[8];
    const float* b1    = (const float*)d_in[9];
    const float* W2    = (const float*)d_in[10];
    const float* b2    = (const float*)d_in[11];

    float* out    = (float*)d_out;
    float* H_curr = out + 2;

    setup_kernel<<<1, 256>>>(mask);
    gru_main_kernel<<<NBLK, BTH>>>(X, mask, Ht, xT_w, xT_b, U_w, H_curr);
    finalize_kernel<<<1, 1024>>>(W1, b1, W2, b2, out);
}

// round 15
// speedup vs baseline: 1.0156x; 1.0156x over previous
#include <cuda_runtime.h>
#include <cuda_bf16.h>
#include <math.h>

// Problem constants
#define NF   16384
#define HID  64
#define TH   192          // 3*HID rows of U per feature
#define FPB  4            // features per block (fine-grained tail)
#define NBLK (NF / FPB)   // 4096
#define BTH  256          // 8 warps; warp w owns gates [8w, 8w+8)

// Static scratch
__device__ float g_partial_agg[NBLK * HID];
__device__ int   g_any_mask;      // written by setup_kernel (pre-main)
__device__ int   g_mask_mode;

__device__ __forceinline__ float dot4(float4 a, float4 b) {
    return a.x * b.x + a.y * b.y + a.z * b.z + a.w * b.w;
}

__device__ __forceinline__ bool mask_at(const void* mp, int mode, int f) {
    if (mode == 0) return ((const unsigned char*)mp)[f] != 0;
    if (mode == 1) return ((const int*)mp)[f] != 0;
    return ((const float*)mp)[f] != 0.0f;
}

__device__ __forceinline__ float red8(float v) {
    v += __shfl_xor_sync(0xFFFFFFFFu, v, 1);
    v += __shfl_xor_sync(0xFFFFFFFFu, v, 2);
    v += __shfl_xor_sync(0xFFFFFFFFu, v, 4);
    return v;
}

// ---------------------------------------------------------------------------
// Kernel 0: detect mask representation (0=u8 bool, 1=i32, 2=f32) and compute
// any(mask) with an EARLY-EXIT chunked scan (one chunk in the common case —
// R14's full count here cost 12.7us on the pre-main critical path).
// The full count is deferred to finalize_kernel, which runs post-main.
// ---------------------------------------------------------------------------
__global__ __launch_bounds__(256) void setup_kernel(const void* __restrict__ mask)
{
    __shared__ int s_isf, s_isu8;
    const int t = threadIdx.x;

    if (t == 0) { s_isf = 0; s_isu8 = 0; }
    __syncthreads();

    // representation probe on the first 256 bytes / 64 words
    {
        const unsigned int*  mw = (const unsigned int*)mask;
        const unsigned char* mb = (const unsigned char*)mask;
        if (t < 64 && mw[t] == 0x3F800000u) atomicOr(&s_isf, 1);
        if ((t & 3) != 0 && mb[t] != 0)     atomicOr(&s_isu8, 1);
    }
    __syncthreads();
    const int mode = s_isf ? 2 : (s_isu8 ? 0 : 1);
    if (t == 0) g_mask_mode = mode;

    // any(mask): chunked scan, exits after the first chunk with a set bit
    int any = 0;
    #pragma unroll 1
    for (int base = 0; base < NF; base += 256) {
        const int p = (int)mask_at(mask, mode, base + t);
        if (__syncthreads_or(p)) { any = 1; break; }
    }
    if (t == 0) g_any_mask = any;
}

// ---------------------------------------------------------------------------
// Kernel 1: per-feature GRU cell — barrier-free main loop.
// Warp w owns gates g0 = 8w+rsub, g1 = g0+4 (rsub = lane>>3). Its 6 row-dots
// per feature are exactly the z/r/h rows of those two gates. 8 lanes per row
// (q = lane&7 reads the q-th float4 of each 128B half-row) -> every LDG.128
// covers 4 rows x one full 128B line. 3-level shfl.xor gives all lanes all
// 6 dots; lanes q=0/q=1 finish gates g0/g1 entirely in registers.
// No-mask fallback folded into the store: mv ? hg : (any ? 0 : htg).
// ---------------------------------------------------------------------------
__global__ __launch_bounds__(BTH, 4) void gru_main_kernel(
    const float* __restrict__ X,
    const void*  __restrict__ mask,
    const float* __restrict__ Ht,
    const float* __restrict__ xT_w,   // (F, 192, 1)
    const float* __restrict__ xT_b,   // (F, 192)
    const float* __restrict__ U_w,    // (F, 192, 64)
    float*       __restrict__ H_curr) // (F, 64)
{
    const int t    = threadIdx.x;
    const int w    = t >> 5;
    const int l    = t & 31;
    const int q    = l & 7;
    const int rsub = l >> 3;
    const int g0   = 8 * w + rsub;
    const int g1   = g0 + 4;
    const int g    = (q == 0) ? g0 : g1;   // gate owned by lanes q<2

    const int  mode = g_mask_mode;         // broadcast, set by setup_kernel
    const bool any  = (g_any_mask != 0);   // broadcast, set by setup_kernel

    float agg0 = 0.0f, agg1 = 0.0f;

    #pragma unroll 1
    for (int j = 0; j < FPB; j++) {
        const int f = blockIdx.x * FPB + j;

        // Ht slices first: they sit on the FFMA dependency chain
        const float4* Ht4 = (const float4*)(Ht + (size_t)f * HID);
        const float4  h0  = Ht4[q];
        const float4  h1  = Ht4[8 + q];

        // 12 front-batched streaming LDG.128 (rows of this warp's two gates)
        const float4* Ub = (const float4*)(U_w + (size_t)f * TH * HID);
        const float4 uA0 = __ldcs(Ub + (g0      ) * 16 + q);
        const float4 uB0 = __ldcs(Ub + (g0      ) * 16 + 8 + q);
        const float4 uA1 = __ldcs(Ub + (g0 +  64) * 16 + q);
        const float4 uB1 = __ldcs(Ub + (g0 +  64) * 16 + 8 + q);
        const float4 uA2 = __ldcs(Ub + (g0 + 128) * 16 + q);
        const float4 uB2 = __ldcs(Ub + (g0 + 128) * 16 + 8 + q);
        const float4 uA3 = __ldcs(Ub + (g1      ) * 16 + q);
        const float4 uB3 = __ldcs(Ub + (g1      ) * 16 + 8 + q);
        const float4 uA4 = __ldcs(Ub + (g1 +  64) * 16 + q);
        const float4 uB4 = __ldcs(Ub + (g1 +  64) * 16 + 8 + q);
        const float4 uA5 = __ldcs(Ub + (g1 + 128) * 16 + q);
        const float4 uB5 = __ldcs(Ub + (g1 + 128) * 16 + 8 + q);

        // Gate-lane scalars (independent; small L1-shared lines)
        float xz = 0.f, xr = 0.f, xh = 0.f, htg = 0.f;
        bool  mv = false;
        if (q < 2) {
            const float xf = X[f];
            const float* xw = xT_w + (size_t)f * TH;
            const float* xb = xT_b + (size_t)f * TH;
            xz  = fmaf(xw[g],       xf, xb[g]);
            xr  = fmaf(xw[g + 64],  xf, xb[g + 64]);
            xh  = fmaf(xw[g + 128], xf, xb[g + 128]);
            htg = Ht[(size_t)f * HID + g];
            mv  = mask_at(mask, mode, f);
        }

        float d0 = dot4(uA0, h0) + dot4(uB0, h1);
        float d1 = dot4(uA1, h0) + dot4(uB1, h1);
        float d2 = dot4(uA2, h0) + dot4(uB2, h1);
        float d3 = dot4(uA3, h0) + dot4(uB3, h1);
        float d4 = dot4(uA4, h0) + dot4(uB4, h1);
        float d5 = dot4(uA5, h0) + dot4(uB5, h1);

        d0 = red8(d0); d1 = red8(d1); d2 = red8(d2);
        d3 = red8(d3); d4 = red8(d4); d5 = red8(d5);

        if (q < 2) {
            const float uz = (q == 0) ? d0 : d3;
            const float ur = (q == 0) ? d1 : d4;
            const float uh = (q == 0) ? d2 : d5;

            const float z   = 1.0f / (1.0f + __expf(-(xz + uz)));
            const float r   = 1.0f / (1.0f + __expf(-(xr + ur)));
            const float htl = tanhf(xh + r * uh);
            const float hg  = z * htg + (1.0f - z) * htl;

            // reference: H_curr = where(mask, h_gate, 0); where(any, ., Ht)
            const float outv = mv ? hg : (any ? 0.0f : htg);
            __stcs(H_curr + (size_t)f * HID + g, outv);
            const float add = mv ? hg : 0.0f;
            if (q == 0) agg0 += add; else agg1 += add;
        }
    }

    if (q == 0) g_partial_agg[blockIdx.x * HID + g0] = agg0;
    if (q == 1) g_partial_agg[blockIdx.x * HID + g1] = agg1;
}

// ---------------------------------------------------------------------------
// Kernel 2: reduce partials (coalesced 16-slice) + count mask in parallel,
// then MLP head + softmax. Runs post-main, so the count is off the critical
// path of the big kernel.
// ---------------------------------------------------------------------------
__global__ __launch_bounds__(1024) void finalize_kernel(
    const void*  __restrict__ mask,
    const float* __restrict__ W1,
    const float* __restrict__ b1,
    const float* __restrict__ W2,
    const float* __restrict__ b2,
    float*       __restrict__ out)
{
    __shared__ float red[16][HID];
    __shared__ float sAgg[HID];
    __shared__ float sHid[HID];
    __shared__ int   scnt;

    const int t  = threadIdx.x;
    const int h  = t & 63;
    const int sl = t >> 6;

    if (t == 0) scnt = 0;
    __syncthreads();

    // mask count: 16 elements per thread, parallel with agg reduction below
    {
        const int mode = g_mask_mode;
        int c = 0;
        #pragma unroll
        for (int i = 0; i < NF / 1024; i++)
            c += (int)mask_at(mask, mode, i * 1024 + t);
        c += __shfl_xor_sync(0xFFFFFFFFu, c, 1);
        c += __shfl_xor_sync(0xFFFFFFFFu, c, 2);
        c += __shfl_xor_sync(0xFFFFFFFFu, c, 4);
        c += __shfl_xor_sync(0xFFFFFFFFu, c, 8);
        c += __shfl_xor_sync(0xFFFFFFFFu, c, 16);
        if ((t & 31) == 0) atomicAdd(&scnt, c);
    }

    float a = 0.0f;
    #pragma unroll 8
    for (int bb = sl; bb < NBLK; bb += 16) a += g_partial_agg[bb * HID + h];
    red[sl][h] = a;
    __syncthreads();

    if (t < HID) {
        float s = 0.0f;
        #pragma unroll
        for (int i = 0; i < 16; i++) s += red[i][t];
        sAgg[t] = s / fmaxf((float)scnt, 1.0f);
    }
    __syncthreads();

    if (t < HID) {
        float acc = b1[t];
        #pragma unroll 8
        for (int k = 0; k < HID; k++) acc += sAgg[k] * W1[k * HID + t];
        sHid[t] = fmaxf(acc, 0.0f);
    }
    __syncthreads();

    if (t == 0) {
        float l0 = b2[0], l1 = b2[1];
        #pragma unroll 8
        for (int j = 0; j < HID; j++) {
            l0 += sHid[j] * W2[j * 2 + 0];
            l1 += sHid[j] * W2[j * 2 + 1];
        }
        const float mx = fmaxf(l0, l1);
        const float e0 = expf(l0 - mx), e1 = expf(l1 - mx);
        const float inv = 1.0f / (e0 + e1);
        out[0] = e0 * inv;
        out[1] = e1 * inv;
    }
}

// ---------------------------------------------------------------------------
// Launch.  Inputs: tim, X, X_hap, mask, Ht, xT_w, xT_b, U_w, W1, b1, W2, b2.
// Output: [pred(2), H_curr(16384*64)] float32.
// ---------------------------------------------------------------------------
extern "C" void kernel_launch(void* const* d_in, const int* in_sizes, int n_in,
                              void* d_out, int out_size)
{
    const float* X     = (const float*)d_in[1];
    const void*  mask  = d_in[3];
    const float* Ht    = (const float*)d_in[4];
    const float* xT_w  = (const float*)d_in[5];
    const float* xT_b  = (const float*)d_in[6];
    const float* U_w   = (const float*)d_in[7];
    const float* W1    = (const float*)d_in[8];
    const float* b1    = (const float*)d_in[9];
    const float* W2    = (const float*)d_in[10];
    const float* b2    = (const float*)d_in[11];

    float* out    = (float*)d_out;
    float* H_curr = out + 2;

    setup_kernel<<<1, 256>>>(mask);
    gru_main_kernel<<<NBLK, BTH>>>(X, mask, Ht, xT_w, xT_b, U_w, H_curr);
    finalize_kernel<<<1, 1024>>>(mask, W1, b1, W2, b2, out);
}

// round 16
// speedup vs baseline: 1.0262x; 1.0104x over previous
#include <cuda_runtime.h>
#include <cuda_bf16.h>
#include <math.h>

// Problem constants
#define NF   16384
#define HID  64
#define TH   192          // 3*HID rows of U per feature
#define FPB  4            // features per block (fine-grained tail)
#define NBLK (NF / FPB)   // 4096
#define BTH  256          // 8 warps; warp w owns gates [8w, 8w+8)

// Static scratch
__device__ float g_partial_agg[NBLK * HID];

__device__ __forceinline__ float dot4(float4 a, float4 b) {
    return a.x * b.x + a.y * b.y + a.z * b.z + a.w * b.w;
}

__device__ __forceinline__ bool mask_at(const void* mp, int mode, int f) {
    if (mode == 0) return ((const unsigned char*)mp)[f] != 0;
    if (mode == 1) return ((const int*)mp)[f] != 0;
    return ((const float*)mp)[f] != 0.0f;
}

__device__ __forceinline__ float red8(float v) {
    v += __shfl_xor_sync(0xFFFFFFFFu, v, 1);
    v += __shfl_xor_sync(0xFFFFFFFFu, v, 2);
    v += __shfl_xor_sync(0xFFFFFFFFu, v, 4);
    return v;
}

// Per-warp mask-representation detection from the first 256 bytes / 64 words.
// 0 = u8 bool, 1 = i32, 2 = f32. Two LDGs per lane, two ballots, no barrier.
// f32 check first (a 1.0f word also trips the off-aligned-byte test).
__device__ __forceinline__ int detect_mode_warp(const void* mp, int l) {
    const unsigned* mw = (const unsigned*)mp;
    const unsigned wa = mw[l], wb = mw[l + 32];
    const bool isf  = (wa == 0x3F800000u) || (wb == 0x3F800000u);
    const bool isu8 = ((wa & 0xFFFFFF00u) != 0u) || ((wb & 0xFFFFFF00u) != 0u);
    const unsigned bf = __ballot_sync(0xFFFFFFFFu, isf);
    const unsigned bu = __ballot_sync(0xFFFFFFFFu, isu8);
    return bf ? 2 : (bu ? 0 : 1);
}

// ---------------------------------------------------------------------------
// Kernel 1: per-feature GRU cell — barrier-free, self-contained (no setup
// kernel: mode detection + early-exit any(mask) scan run per-warp in the
// prologue; with a random mask the any-scan terminates on its first chunk).
// Warp w owns gates g0 = 8w+rsub, g1 = g0+4 (rsub = lane>>3). Its 6 row-dots
// per feature are exactly the z/r/h rows of those two gates. 8 lanes per row
// (q = lane&7 reads the q-th float4 of each 128B half-row) -> every LDG.128
// covers 4 rows x one full 128B line. 3-level shfl.xor gives all lanes all
// 6 dots; lanes q=0/q=1 finish gates g0/g1 entirely in registers.
// No-mask fallback folded into the store: mv ? hg : (any ? 0 : htg).
// ---------------------------------------------------------------------------
__global__ __launch_bounds__(BTH, 4) void gru_main_kernel(
    const float* __restrict__ X,
    const void*  __restrict__ mask,
    const float* __restrict__ Ht,
    const float* __restrict__ xT_w,   // (F, 192, 1)
    const float* __restrict__ xT_b,   // (F, 192)
    const float* __restrict__ U_w,    // (F, 192, 64)
    float*       __restrict__ H_curr) // (F, 64)
{
    const int t    = threadIdx.x;
    const int w    = t >> 5;
    const int l    = t & 31;
    const int q    = l & 7;
    const int rsub = l >> 3;
    const int g0   = 8 * w + rsub;
    const int g1   = g0 + 4;
    const int g    = (q == 0) ? g0 : g1;   // gate owned by lanes q<2

    // prologue: mode + any(mask), per-warp, no barriers
    const int mode = detect_mode_warp(mask, l);
    bool any = false;
    #pragma unroll 1
    for (int base = 0; base < NF; base += 32) {
        if (__ballot_sync(0xFFFFFFFFu, mask_at(mask, mode, base + l))) {
            any = true; break;
        }
    }

    float agg0 = 0.0f, agg1 = 0.0f;

    #pragma unroll 1
    for (int j = 0; j < FPB; j++) {
        const int f = blockIdx.x * FPB + j;

        // Ht slices first: they sit on the FFMA dependency chain
        const float4* Ht4 = (const float4*)(Ht + (size_t)f * HID);
        const float4  h0  = Ht4[q];
        const float4  h1  = Ht4[8 + q];

        // 12 front-batched streaming LDG.128 (rows of this warp's two gates)
        const float4* Ub = (const float4*)(U_w + (size_t)f * TH * HID);
        const float4 uA0 = __ldcs(Ub + (g0      ) * 16 + q);
        const float4 uB0 = __ldcs(Ub + (g0      ) * 16 + 8 + q);
        const float4 uA1 = __ldcs(Ub + (g0 +  64) * 16 + q);
        const float4 uB1 = __ldcs(Ub + (g0 +  64) * 16 + 8 + q);
        const float4 uA2 = __ldcs(Ub + (g0 + 128) * 16 + q);
        const float4 uB2 = __ldcs(Ub + (g0 + 128) * 16 + 8 + q);
        const float4 uA3 = __ldcs(Ub + (g1      ) * 16 + q);
        const float4 uB3 = __ldcs(Ub + (g1      ) * 16 + 8 + q);
        const float4 uA4 = __ldcs(Ub + (g1 +  64) * 16 + q);
        const float4 uB4 = __ldcs(Ub + (g1 +  64) * 16 + 8 + q);
        const float4 uA5 = __ldcs(Ub + (g1 + 128) * 16 + q);
        const float4 uB5 = __ldcs(Ub + (g1 + 128) * 16 + 8 + q);

        // Gate-lane scalars (independent; small L1-shared lines)
        float xz = 0.f, xr = 0.f, xh = 0.f, htg = 0.f;
        bool  mv = false;
        if (q < 2) {
            const float xf = X[f];
            const float* xw = xT_w + (size_t)f * TH;
            const float* xb = xT_b + (size_t)f * TH;
            xz  = fmaf(xw[g],       xf, xb[g]);
            xr  = fmaf(xw[g + 64],  xf, xb[g + 64]);
            xh  = fmaf(xw[g + 128], xf, xb[g + 128]);
            htg = Ht[(size_t)f * HID + g];
            mv  = mask_at(mask, mode, f);
        }

        float d0 = dot4(uA0, h0) + dot4(uB0, h1);
        float d1 = dot4(uA1, h0) + dot4(uB1, h1);
        float d2 = dot4(uA2, h0) + dot4(uB2, h1);
        float d3 = dot4(uA3, h0) + dot4(uB3, h1);
        float d4 = dot4(uA4, h0) + dot4(uB4, h1);
        float d5 = dot4(uA5, h0) + dot4(uB5, h1);

        d0 = red8(d0); d1 = red8(d1); d2 = red8(d2);
        d3 = red8(d3); d4 = red8(d4); d5 = red8(d5);

        if (q < 2) {
            const float uz = (q == 0) ? d0 : d3;
            const float ur = (q == 0) ? d1 : d4;
            const float uh = (q == 0) ? d2 : d5;

            const float z   = 1.0f / (1.0f + __expf(-(xz + uz)));
            const float r   = 1.0f / (1.0f + __expf(-(xr + ur)));
            const float htl = tanhf(xh + r * uh);
            const float hg  = z * htg + (1.0f - z) * htl;

            // reference: H_curr = where(mask, h_gate, 0); where(any, ., Ht)
            const float outv = mv ? hg : (any ? 0.0f : htg);
            __stcs(H_curr + (size_t)f * HID + g, outv);
            const float add = mv ? hg : 0.0f;
            if (q == 0) agg0 += add; else agg1 += add;
        }
    }

    if (q == 0) g_partial_agg[blockIdx.x * HID + g0] = agg0;
    if (q == 1) g_partial_agg[blockIdx.x * HID + g1] = agg1;
}

// ---------------------------------------------------------------------------
// Kernel 2: reduce partials (coalesced 16-slice) + count mask in parallel,
// then MLP head + softmax. Runs post-main; detects mode itself (per-warp).
// ---------------------------------------------------------------------------
__global__ __launch_bounds__(1024) void finalize_kernel(
    const void*  __restrict__ mask,
    const float* __restrict__ W1,
    const float* __restrict__ b1,
    const float* __restrict__ W2,
    const float* __restrict__ b2,
    float*       __restrict__ out)
{
    __shared__ float red[16][HID];
    __shared__ float sAgg[HID];
    __shared__ float sHid[HID];
    __shared__ int   scnt;

    const int t  = threadIdx.x;
    const int l  = t & 31;
    const int h  = t & 63;
    const int sl = t >> 6;

    if (t == 0) scnt = 0;
    __syncthreads();

    // mask count: 16 elements per thread, parallel with agg reduction below
    {
        const int mode = detect_mode_warp(mask, l);
        int c = 0;
        #pragma unroll
        for (int i = 0; i < NF / 1024; i++)
            c += (int)mask_at(mask, mode, i * 1024 + t);
        c += __shfl_xor_sync(0xFFFFFFFFu, c, 1);
        c += __shfl_xor_sync(0xFFFFFFFFu, c, 2);
        c += __shfl_xor_sync(0xFFFFFFFFu, c, 4);
        c += __shfl_xor_sync(0xFFFFFFFFu, c, 8);
        c += __shfl_xor_sync(0xFFFFFFFFu, c, 16);
        if (l == 0) atomicAdd(&scnt, c);
    }

    float a = 0.0f;
    #pragma unroll 8
    for (int bb = sl; bb < NBLK; bb += 16) a += g_partial_agg[bb * HID + h];
    red[sl][h] = a;
    __syncthreads();

    if (t < HID) {
        float s = 0.0f;
        #pragma unroll
        for (int i = 0; i < 16; i++) s += red[i][t];
        sAgg[t] = s / fmaxf((float)scnt, 1.0f);
    }
    __syncthreads();

    if (t < HID) {
        float acc = b1[t];
        #pragma unroll 8
        for (int k = 0; k < HID; k++) acc += sAgg[k] * W1[k * HID + t];
        sHid[t] = fmaxf(acc, 0.0f);
    }
    __syncthreads();

    if (t == 0) {
        float l0 = b2[0], l1 = b2[1];
        #pragma unroll 8
        for (int j = 0; j < HID; j++) {
            l0 += sHid[j] * W2[j * 2 + 0];
            l1 += sHid[j] * W2[j * 2 + 1];
        }
        const float mx = fmaxf(l0, l1);
        const float e0 = expf(l0 - mx), e1 = expf(l1 - mx);
        const float inv = 1.0f / (e0 + e1);
        out[0] = e0 * inv;
        out[1] = e1 * inv;
    }
}

// ---------------------------------------------------------------------------
// Launch.  Inputs: tim, X, X_hap, mask, Ht, xT_w, xT_b, U_w, W1, b1, W2, b2.
// Output: [pred(2), H_curr(16384*64)] float32.
// ---------------------------------------------------------------------------
extern "C" void kernel_launch(void* const* d_in, const int* in_sizes, int n_in,
                              void* d_out, int out_size)
{
    const float* X     = (const float*)d_in[1];
    const void*  mask  = d_in[3];
    const float* Ht    = (const float*)d_in[4];
    const float* xT_w  = (const float*)d_in[5];
    const float* xT_b  = (const float*)d_in[6];
    const float* U_w   = (const float*)d_in[7];
    const float* W1    = (const float*)d_in[8];
    const float* b1    = (const float*)d_in[9];
    const float* W2    = (const float*)d_in[10];
    const float* b2    = (const float*)d_in[11];

    float* out    = (float*)d_out;
    float* H_curr = out + 2;

    gru_main_kernel<<<NBLK, BTH>>>(X, mask, Ht, xT_w, xT_b, U_w, H_curr);
    finalize_kernel<<<1, 1024>>>(mask, W1, b1, W2, b2, out);
}

// round 17
// speedup vs baseline: 1.0961x; 1.0681x over previous
#include <cuda_runtime.h>
#include <cuda_bf16.h>
#include <math.h>

// Problem constants
#define NF   16384
#define HID  64
#define TH   192          // 3*HID rows of U per feature
#define FPB  4            // features per block (fine-grained tail)
#define NBLK (NF / FPB)   // 4096
#define BTH  256          // 8 warps; warp w owns gates [8w, 8w+8)
#define NSTG 256          // stage-reduction blocks
#define RPB  (NBLK / NSTG) // 16 partial rows per stage block

// Static scratch
__device__ float g_partial_agg[NBLK * HID];
__device__ float g_stage[NSTG * HID];

__device__ __forceinline__ float dot4(float4 a, float4 b) {
    return a.x * b.x + a.y * b.y + a.z * b.z + a.w * b.w;
}

__device__ __forceinline__ bool mask_at(const void* mp, int mode, int f) {
    if (mode == 0) return ((const unsigned char*)mp)[f] != 0;
    if (mode == 1) return ((const int*)mp)[f] != 0;
    return ((const float*)mp)[f] != 0.0f;
}

__device__ __forceinline__ float red8(float v) {
    v += __shfl_xor_sync(0xFFFFFFFFu, v, 1);
    v += __shfl_xor_sync(0xFFFFFFFFu, v, 2);
    v += __shfl_xor_sync(0xFFFFFFFFu, v, 4);
    return v;
}

// Per-warp mask-representation detection from the first 256 bytes / 64 words.
// 0 = u8 bool, 1 = i32, 2 = f32. Two LDGs per lane, two ballots, no barrier.
__device__ __forceinline__ int detect_mode_warp(const void* mp, int l) {
    const unsigned* mw = (const unsigned*)mp;
    const unsigned wa = mw[l], wb = mw[l + 32];
    const bool isf  = (wa == 0x3F800000u) || (wb == 0x3F800000u);
    const bool isu8 = ((wa & 0xFFFFFF00u) != 0u) || ((wb & 0xFFFFFF00u) != 0u);
    const unsigned bf = __ballot_sync(0xFFFFFFFFu, isf);
    const unsigned bu = __ballot_sync(0xFFFFFFFFu, isu8);
    return bf ? 2 : (bu ? 0 : 1);
}

// ---------------------------------------------------------------------------
// Kernel 1: per-feature GRU cell — unchanged champion (R16).
// Barrier-free; per-warp mode detection + early-exit any(mask) prologue.
// Warp w owns gates g0 = 8w+rsub, g1 = g0+4; 8 lanes per U row -> every
// LDG.128 covers 4 rows x one full 128B line; 3-level shfl.xor reduction.
// No-mask fallback folded into the store.
// ---------------------------------------------------------------------------
__global__ __launch_bounds__(BTH, 4) void gru_main_kernel(
    const float* __restrict__ X,
    const void*  __restrict__ mask,
    const float* __restrict__ Ht,
    const float* __restrict__ xT_w,   // (F, 192, 1)
    const float* __restrict__ xT_b,   // (F, 192)
    const float* __restrict__ U_w,    // (F, 192, 64)
    float*       __restrict__ H_curr) // (F, 64)
{
    const int t    = threadIdx.x;
    const int w    = t >> 5;
    const int l    = t & 31;
    const int q    = l & 7;
    const int rsub = l >> 3;
    const int g0   = 8 * w + rsub;
    const int g1   = g0 + 4;
    const int g    = (q == 0) ? g0 : g1;   // gate owned by lanes q<2

    // prologue: mode + any(mask), per-warp, no barriers
    const int mode = detect_mode_warp(mask, l);
    bool any = false;
    #pragma unroll 1
    for (int base = 0; base < NF; base += 32) {
        if (__ballot_sync(0xFFFFFFFFu, mask_at(mask, mode, base + l))) {
            any = true; break;
        }
    }

    float agg0 = 0.0f, agg1 = 0.0f;

    #pragma unroll 1
    for (int j = 0; j < FPB; j++) {
        const int f = blockIdx.x * FPB + j;

        // Ht slices first: they sit on the FFMA dependency chain
        const float4* Ht4 = (const float4*)(Ht + (size_t)f * HID);
        const float4  h0  = Ht4[q];
        const float4  h1  = Ht4[8 + q];

        // 12 front-batched streaming LDG.128 (rows of this warp's two gates)
        const float4* Ub = (const float4*)(U_w + (size_t)f * TH * HID);
        const float4 uA0 = __ldcs(Ub + (g0      ) * 16 + q);
        const float4 uB0 = __ldcs(Ub + (g0      ) * 16 + 8 + q);
        const float4 uA1 = __ldcs(Ub + (g0 +  64) * 16 + q);
        const float4 uB1 = __ldcs(Ub + (g0 +  64) * 16 + 8 + q);
        const float4 uA2 = __ldcs(Ub + (g0 + 128) * 16 + q);
        const float4 uB2 = __ldcs(Ub + (g0 + 128) * 16 + 8 + q);
        const float4 uA3 = __ldcs(Ub + (g1      ) * 16 + q);
        const float4 uB3 = __ldcs(Ub + (g1      ) * 16 + 8 + q);
        const float4 uA4 = __ldcs(Ub + (g1 +  64) * 16 + q);
        const float4 uB4 = __ldcs(Ub + (g1 +  64) * 16 + 8 + q);
        const float4 uA5 = __ldcs(Ub + (g1 + 128) * 16 + q);
        const float4 uB5 = __ldcs(Ub + (g1 + 128) * 16 + 8 + q);

        // Gate-lane scalars (independent; small L1-shared lines)
        float xz = 0.f, xr = 0.f, xh = 0.f, htg = 0.f;
        bool  mv = false;
        if (q < 2) {
            const float xf = X[f];
            const float* xw = xT_w + (size_t)f * TH;
            const float* xb = xT_b + (size_t)f * TH;
            xz  = fmaf(xw[g],       xf, xb[g]);
            xr  = fmaf(xw[g + 64],  xf, xb[g + 64]);
            xh  = fmaf(xw[g + 128], xf, xb[g + 128]);
            htg = Ht[(size_t)f * HID + g];
            mv  = mask_at(mask, mode, f);
        }

        float d0 = dot4(uA0, h0) + dot4(uB0, h1);
        float d1 = dot4(uA1, h0) + dot4(uB1, h1);
        float d2 = dot4(uA2, h0) + dot4(uB2, h1);
        float d3 = dot4(uA3, h0) + dot4(uB3, h1);
        float d4 = dot4(uA4, h0) + dot4(uB4, h1);
        float d5 = dot4(uA5, h0) + dot4(uB5, h1);

        d0 = red8(d0); d1 = red8(d1); d2 = red8(d2);
        d3 = red8(d3); d4 = red8(d4); d5 = red8(d5);

        if (q < 2) {
            const float uz = (q == 0) ? d0 : d3;
            const float ur = (q == 0) ? d1 : d4;
            const float uh = (q == 0) ? d2 : d5;

            const float z   = 1.0f / (1.0f + __expf(-(xz + uz)));
            const float r   = 1.0f / (1.0f + __expf(-(xr + ur)));
            const float htl = tanhf(xh + r * uh);
            const float hg  = z * htg + (1.0f - z) * htl;

            // reference: H_curr = where(mask, h_gate, 0); where(any, ., Ht)
            const float outv = mv ? hg : (any ? 0.0f : htg);
            __stcs(H_curr + (size_t)f * HID + g, outv);
            const float add = mv ? hg : 0.0f;
            if (q == 0) agg0 += add; else agg1 += add;
        }
    }

    if (q == 0) g_partial_agg[blockIdx.x * HID + g0] = agg0;
    if (q == 1) g_partial_agg[blockIdx.x * HID + g1] = agg1;
}

// ---------------------------------------------------------------------------
// Kernel 2: stage reduction. Block b sums 16 consecutive partial rows into
// g_stage[b]. 1 MB of partials read by 256 parallel blocks (vs R16's single
// block = 39.5us cold). 4 coalesced loads/thread + one smem combine.
// ---------------------------------------------------------------------------
__global__ __launch_bounds__(256) void stage_kernel()
{
    __shared__ float s[4][HID];
    const int t   = threadIdx.x;
    const int b   = blockIdx.x;
    const int h   = t & 63;
    const int sub = t >> 6;          // 0..3

    const int r0 = b * RPB + sub * 4;
    float a = 0.0f;
    #pragma unroll
    for (int i = 0; i < 4; i++)
        a += g_partial_agg[(r0 + i) * HID + h];
    s[sub][h] = a;
    __syncthreads();

    if (t < HID)
        g_stage[b * HID + t] = (s[0][t] + s[1][t]) + (s[2][t] + s[3][t]);
}

// ---------------------------------------------------------------------------
// Kernel 3: reduce 256 stage rows + count mask in parallel, MLP head, softmax.
// ---------------------------------------------------------------------------
__global__ __launch_bounds__(1024) void finalize_kernel(
    const void*  __restrict__ mask,
    const float* __restrict__ W1,
    const float* __restrict__ b1,
    const float* __restrict__ W2,
    const float* __restrict__ b2,
    float*       __restrict__ out)
{
    __shared__ float red[16][HID];
    __shared__ float sAgg[HID];
    __shared__ float sHid[HID];
    __shared__ int   scnt;

    const int t  = threadIdx.x;
    const int l  = t & 31;
    const int h  = t & 63;
    const int sl = t >> 6;

    if (t == 0) scnt = 0;
    __syncthreads();

    // mask count: 16 elements per thread, loads overlap stage-row loads below
    {
        const int mode = detect_mode_warp(mask, l);
        int c = 0;
        #pragma unroll
        for (int i = 0; i < NF / 1024; i++)
            c += (int)mask_at(mask, mode, i * 1024 + t);
        c += __shfl_xor_sync(0xFFFFFFFFu, c, 1);
        c += __shfl_xor_sync(0xFFFFFFFFu, c, 2);
        c += __shfl_xor_sync(0xFFFFFFFFu, c, 4);
        c += __shfl_xor_sync(0xFFFFFFFFu, c, 8);
        c += __shfl_xor_sync(0xFFFFFFFFu, c, 16);
        if (l == 0) atomicAdd(&scnt, c);
    }

    float a = 0.0f;
    #pragma unroll
    for (int bb = sl; bb < NSTG; bb += 16) a += g_stage[bb * HID + h];
    red[sl][h] = a;
    __syncthreads();

    if (t < HID) {
        float s = 0.0f;
        #pragma unroll
        for (int i = 0; i < 16; i++) s += red[i][t];
        sAgg[t] = s / fmaxf((float)scnt, 1.0f);
    }
    __syncthreads();

    if (t < HID) {
        float acc = b1[t];
        #pragma unroll 8
        for (int k = 0; k < HID; k++) acc += sAgg[k] * W1[k * HID + t];
        sHid[t] = fmaxf(acc, 0.0f);
    }
    __syncthreads();

    if (t == 0) {
        float l0 = b2[0], l1 = b2[1];
        #pragma unroll 8
        for (int j = 0; j < HID; j++) {
            l0 += sHid[j] * W2[j * 2 + 0];
            l1 += sHid[j] * W2[j * 2 + 1];
        }
        const float mx = fmaxf(l0, l1);
        const float e0 = expf(l0 - mx), e1 = expf(l1 - mx);
        const float inv = 1.0f / (e0 + e1);
        out[0] = e0 * inv;
        out[1] = e1 * inv;
    }
}

// ---------------------------------------------------------------------------
// Launch.  Inputs: tim, X, X_hap, mask, Ht, xT_w, xT_b, U_w, W1, b1, W2, b2.
// Output: [pred(2), H_curr(16384*64)] float32.
// ---------------------------------------------------------------------------
extern "C" void kernel_launch(void* const* d_in, const int* in_sizes, int n_in,
                              void* d_out, int out_size)
{
    const float* X     = (const float*)d_in[1];
    const void*  mask  = d_in[3];
    const float* Ht    = (const float*)d_in[4];
    const float* xT_w  = (const float*)d_in[5];
    const float* xT_b  = (const float*)d_in[6];
    const float* U_w   = (const float*)d_in[7];
    const float* W1    = (const float*)d_in[8];
    const float* b1    = (const float*)d_in[9];
    const float* W2    = (const float*)d_in[10];
    const float* b2    = (const float*)d_in[11];

    float* out    = (float*)d_out;
    float* H_curr = out + 2;

    gru_main_kernel<<<NBLK, BTH>>>(X, mask, Ht, xT_w, xT_b, U_w, H_curr);
    stage_kernel<<<NSTG, 256>>>();
    finalize_kernel<<<1, 1024>>>(mask, W1, b1, W2, b2, out);
}